// round 9
// baseline (speedup 1.0000x reference)
#include <cuda_runtime.h>
#include <cuda_bf16.h>
#include <cstdint>

// B=16, S=2048, D=128 fp32.
// weights[b,q,k] = softmax_k over {k>=q} of <K[b,q,:],Q[b,k,:]>/sqrt(D); 0 elsewhere.
// outputs = weights @ V.   d_out = [outputs | weights].
//
// K0: split Q, K*scale, V into bf16 hi/lo 128x128 tiles (linear) in __device__ scratch.
// K1: per (q-tile 128, batch) CTA (LPT order: big CTAs first). mma.sync bf16 3-split
//     GEMMs, fully unrolled. exp in place; PV A-frags packed per k-tile. cp.async
//     double-buffered ingest. Tail: CTA normalizes its own W strip (zero below diag,
//     scale above) — overlapped with other CTAs' compute. No separate norm kernel.

namespace {
constexpr int Bn = 16, S = 2048, D = 128;
constexpr int MT = 128;
constexpr float SCALE = 0.08838834764831845f;  // 1/sqrt(128)

constexpr int TILE_B = 65536;     // one tile pair: hi 32KB + lo 32KB
constexpr int SM_A  = 0;
constexpr int SM_Q  = 65536;
constexpr int SM_V  = 131072;
constexpr int SMEM_SZ = 196608;   // 192 KB
}

__device__ __align__(16) uint8_t g_cvt[(size_t)3 * Bn * 16 * TILE_B];  // [tensor][b][tile]

// ---------------- helpers ----------------
__device__ __forceinline__ uint32_t smem_u32(const void* p) {
    uint32_t a;
    asm("{ .reg .u64 t; cvta.to.shared.u64 t, %1; cvt.u32.u64 %0, t; }" : "=r"(a) : "l"(p));
    return a;
}
__device__ __forceinline__ void ldsm4(uint32_t a, uint32_t& r0, uint32_t& r1,
                                      uint32_t& r2, uint32_t& r3) {
    asm volatile("ldmatrix.sync.aligned.m8n8.x4.shared.b16 {%0,%1,%2,%3}, [%4];"
                 : "=r"(r0), "=r"(r1), "=r"(r2), "=r"(r3) : "r"(a));
}
__device__ __forceinline__ void ldsm4t(uint32_t a, uint32_t& r0, uint32_t& r1,
                                       uint32_t& r2, uint32_t& r3) {
    asm volatile("ldmatrix.sync.aligned.m8n8.x4.trans.shared.b16 {%0,%1,%2,%3}, [%4];"
                 : "=r"(r0), "=r"(r1), "=r"(r2), "=r"(r3) : "r"(a));
}
__device__ __forceinline__ void mma16816(float* c, uint32_t a0, uint32_t a1, uint32_t a2,
                                         uint32_t a3, uint32_t b0, uint32_t b1) {
    asm volatile(
        "mma.sync.aligned.m16n8k16.row.col.f32.bf16.bf16.f32 "
        "{%0,%1,%2,%3}, {%4,%5,%6,%7}, {%8,%9}, {%0,%1,%2,%3};"
        : "+f"(c[0]), "+f"(c[1]), "+f"(c[2]), "+f"(c[3])
        : "r"(a0), "r"(a1), "r"(a2), "r"(a3), "r"(b0), "r"(b1));
}
__device__ __forceinline__ uint32_t pk_bf2(float x, float y) {
    __nv_bfloat162 t;
    t.x = __float2bfloat16(x);
    t.y = __float2bfloat16(y);
    return *(uint32_t*)&t;
}
__device__ __forceinline__ uint32_t pk_bf2_lo(float x, float y, uint32_t hi) {
    __nv_bfloat162 h = *(__nv_bfloat162*)&hi;
    __nv_bfloat162 t;
    t.x = __float2bfloat16(x - __bfloat162float(h.x));
    t.y = __float2bfloat16(y - __bfloat162float(h.y));
    return *(uint32_t*)&t;
}
// swizzled tile byte offset: [128 rows][256B], 16B chunk XOR (row&7)
__device__ __forceinline__ uint32_t sw_off(int row, int chunk) {
    return (uint32_t)(row * 256 + ((chunk ^ (row & 7)) << 4));
}
__device__ __forceinline__ void cpa16(uint32_t sdst, const void* gsrc) {
    asm volatile("cp.async.cg.shared.global [%0], [%1], 16;" :: "r"(sdst), "l"(gsrc));
}
#define CPA_COMMIT() asm volatile("cp.async.commit_group;" ::: "memory")
#define CPA_WAIT0()  asm volatile("cp.async.wait_group 0;" ::: "memory")

// global (linear pre-split tile) -> smem (swizzled), 64KB = hi+lo
__device__ __forceinline__ void tile_load(uint32_t sdst, const uint8_t* g, int tid) {
#pragma unroll
    for (int half = 0; half < 2; half++) {
#pragma unroll
        for (int j = 0; j < 8; j++) {
            int idx = j * 256 + tid;            // 0..2047
            int r = idx >> 4, cc = idx & 15;
            cpa16(sdst + half * 32768 + sw_off(r, cc), g + half * 32768 + (size_t)idx * 16);
        }
    }
}

// ------------------------------- K0: pre-split -------------------------------
__global__ __launch_bounds__(256)
void cvt_k0(const float* __restrict__ Q, const float* __restrict__ K,
            const float* __restrict__ V) {
    const int bx = blockIdx.x;                 // t*256 + b*16 + tile
    const int t = bx >> 8, rem = bx & 255;
    const int b = rem >> 4, tile = rem & 15;
    const float* src = (t == 0 ? Q : (t == 1 ? K : V)) + ((size_t)b * S + tile * 128) * D;
    const float mul = (t == 1) ? SCALE : 1.0f;
    uint8_t* dst = g_cvt + (size_t)bx * TILE_B;
    const int tid = threadIdx.x;
#pragma unroll
    for (int it = 0; it < 8; ++it) {
        int idx = it * 256 + tid;              // 0..2047 (16B chunk id)
        const float* gp = src + (size_t)idx * 8;
        float4 v0 = __ldcs((const float4*)gp);
        float4 v1 = __ldcs((const float4*)(gp + 4));
        v0.x *= mul; v0.y *= mul; v0.z *= mul; v0.w *= mul;
        v1.x *= mul; v1.y *= mul; v1.z *= mul; v1.w *= mul;
        uint32_t h0 = pk_bf2(v0.x, v0.y), h1 = pk_bf2(v0.z, v0.w);
        uint32_t h2 = pk_bf2(v1.x, v1.y), h3 = pk_bf2(v1.z, v1.w);
        uint32_t l0 = pk_bf2_lo(v0.x, v0.y, h0), l1 = pk_bf2_lo(v0.z, v0.w, h1);
        uint32_t l2 = pk_bf2_lo(v1.x, v1.y, h2), l3 = pk_bf2_lo(v1.z, v1.w, h3);
        *(uint4*)(dst + (size_t)idx * 16) = make_uint4(h0, h1, h2, h3);
        *(uint4*)(dst + 32768 + (size_t)idx * 16) = make_uint4(l0, l1, l2, l3);
    }
}

// ------------------------------- K1 -------------------------------
__global__ __launch_bounds__(256, 1)
void attn_k1(float* __restrict__ O, float* __restrict__ W) {
    extern __shared__ char sm[];
    const uint32_t sb = smem_u32(sm);
    const int tid = threadIdx.x, wid = tid >> 5, lane = tid & 31;
    // LPT order: big CTAs (qt=0, 16 chunks) first
    const int qt = blockIdx.x >> 4, b = blockIdx.x & 15;
    const int q0 = qt * MT;
    const int nc = 16 - qt;

    const uint8_t* scrQ = g_cvt + ((size_t)(0 * 256 + b * 16)) * TILE_B;
    const uint8_t* scrK = g_cvt + ((size_t)(1 * 256 + b * 16)) * TILE_B;
    const uint8_t* scrV = g_cvt + ((size_t)(2 * 256 + b * 16)) * TILE_B;

    // prologue: A (= K q-rows, pre-scaled) + Q(0)
    tile_load(sb + SM_A, scrK + (size_t)qt * TILE_B, tid);
    tile_load(sb + SM_Q, scrQ + (size_t)qt * TILE_B, tid);
    CPA_COMMIT();
    CPA_WAIT0();
    __syncthreads();

    float oacc[16][4];
#pragma unroll
    for (int j = 0; j < 16; j++)
#pragma unroll
        for (int e = 0; e < 4; e++) oacc[j][e] = 0.f;
    float rs0 = 0.f, rs1 = 0.f;

    const int lRow = lane & 15, lSel = lane >> 4;
    const int aRow = wid * 16 + lRow;
    const int r0l = wid * 16 + (lane >> 2);
    const int colb = 2 * (lane & 3);

    for (int c = 0; c < nc; ++c) {
        const int tileIdx = qt + c;
        // prefetch V(c) under scores
        tile_load(sb + SM_V, scrV + (size_t)tileIdx * TILE_B, tid);
        CPA_COMMIT();

        // ---- scores (3-split bf16), fully unrolled (static sacc indexing) ----
        float sacc[16][4];
#pragma unroll
        for (int j = 0; j < 16; j++)
#pragma unroll
            for (int e = 0; e < 4; e++) sacc[j][e] = 0.f;
        const bool diag = (c == 0);

#pragma unroll
        for (int ks = 0; ks < 8; ++ks) {
            uint32_t ah0, ah1, ah2, ah3, al0, al1, al2, al3;
            uint32_t aoff = sw_off(aRow, 2 * ks + lSel);
            ldsm4(sb + SM_A + aoff, ah0, ah1, ah2, ah3);
            ldsm4(sb + SM_A + 32768 + aoff, al0, al1, al2, al3);
#pragma unroll
            for (int jt = 0; jt < 8; ++jt) {
                // warp-uniform diagonal triangle skip; jt is compile-time constant
                if (!(diag && jt < wid)) {
                    uint32_t boff = sw_off(jt * 16 + lRow, 2 * ks + lSel);
                    uint32_t bh0, bh1, bh2, bh3, bl0, bl1, bl2, bl3;
                    ldsm4(sb + SM_Q + boff, bh0, bh1, bh2, bh3);
                    ldsm4(sb + SM_Q + 32768 + boff, bl0, bl1, bl2, bl3);
                    mma16816(sacc[2 * jt], ah0, ah1, ah2, ah3, bh0, bh2);
                    mma16816(sacc[2 * jt], al0, al1, al2, al3, bh0, bh2);
                    mma16816(sacc[2 * jt], ah0, ah1, ah2, ah3, bl0, bl2);
                    mma16816(sacc[2 * jt + 1], ah0, ah1, ah2, ah3, bh1, bh3);
                    mma16816(sacc[2 * jt + 1], al0, al1, al2, al3, bh1, bh3);
                    mma16816(sacc[2 * jt + 1], ah0, ah1, ah2, ah3, bl1, bl3);
                }
            }
        }

        // ---- epilogue: exp+mask IN PLACE, unnorm W (__stcs), rowsums ----
        float* w0 = W + ((size_t)(b * S + q0 + r0l)) * S + tileIdx * 128 + colb;
        float* w1 = w0 + (size_t)8 * S;
#pragma unroll
        for (int j = 0; j < 16; j++) {
            const int col = j * 8 + colb;
            float e0 = (!diag || col >= r0l) ? __expf(sacc[j][0]) : 0.f;
            float e1 = (!diag || col + 1 >= r0l) ? __expf(sacc[j][1]) : 0.f;
            float f0 = (!diag || col >= r0l + 8) ? __expf(sacc[j][2]) : 0.f;
            float f1 = (!diag || col + 1 >= r0l + 8) ? __expf(sacc[j][3]) : 0.f;
            rs0 += e0 + e1;
            rs1 += f0 + f1;
            __stcs((float2*)(w0 + j * 8), make_float2(e0, e1));
            __stcs((float2*)(w1 + j * 8), make_float2(f0, f1));
            sacc[j][0] = e0; sacc[j][1] = e1; sacc[j][2] = f0; sacc[j][3] = f1;
        }

        CPA_WAIT0();        // V(c) resident
        __syncthreads();    // all warps done reading Q slot
        if (c + 1 < nc) {   // prefetch Q(c+1) under PV
            tile_load(sb + SM_Q, scrQ + (size_t)(tileIdx + 1) * TILE_B, tid);
            CPA_COMMIT();
        }

        // ---- PV: oacc += Phi*Vhi + Plo*Vhi + Phi*Vlo; P packed per k-tile ----
#pragma unroll
        for (int kt = 0; kt < 8; ++kt) {
            const uint32_t pa0 = pk_bf2(sacc[2 * kt][0], sacc[2 * kt][1]);
            const uint32_t pa1 = pk_bf2(sacc[2 * kt][2], sacc[2 * kt][3]);
            const uint32_t pa2 = pk_bf2(sacc[2 * kt + 1][0], sacc[2 * kt + 1][1]);
            const uint32_t pa3 = pk_bf2(sacc[2 * kt + 1][2], sacc[2 * kt + 1][3]);
            const uint32_t qa0 = pk_bf2_lo(sacc[2 * kt][0], sacc[2 * kt][1], pa0);
            const uint32_t qa1 = pk_bf2_lo(sacc[2 * kt][2], sacc[2 * kt][3], pa1);
            const uint32_t qa2 = pk_bf2_lo(sacc[2 * kt + 1][0], sacc[2 * kt + 1][1], pa2);
            const uint32_t qa3 = pk_bf2_lo(sacc[2 * kt + 1][2], sacc[2 * kt + 1][3], pa3);
            const int krow = kt * 16 + lRow;
#pragma unroll
            for (int dt = 0; dt < 8; ++dt) {
                uint32_t voff = sw_off(krow, 2 * dt + lSel);
                uint32_t vh0, vh1, vh2, vh3, vl0, vl1, vl2, vl3;
                ldsm4t(sb + SM_V + voff, vh0, vh1, vh2, vh3);
                ldsm4t(sb + SM_V + 32768 + voff, vl0, vl1, vl2, vl3);
                mma16816(oacc[2 * dt], pa0, pa1, pa2, pa3, vh0, vh1);
                mma16816(oacc[2 * dt], qa0, qa1, qa2, qa3, vh0, vh1);
                mma16816(oacc[2 * dt], pa0, pa1, pa2, pa3, vl0, vl1);
                mma16816(oacc[2 * dt + 1], pa0, pa1, pa2, pa3, vh2, vh3);
                mma16816(oacc[2 * dt + 1], qa0, qa1, qa2, qa3, vh2, vh3);
                mma16816(oacc[2 * dt + 1], pa0, pa1, pa2, pa3, vl2, vl3);
            }
        }
        CPA_WAIT0();        // Q(c+1) resident
        __syncthreads();    // all warps done reading V slot
    }

    // ---- rowsums -> inverses; scale O; write; publish inv to smem ----
    rs0 += __shfl_xor_sync(0xffffffffu, rs0, 1);
    rs0 += __shfl_xor_sync(0xffffffffu, rs0, 2);
    rs1 += __shfl_xor_sync(0xffffffffu, rs1, 1);
    rs1 += __shfl_xor_sync(0xffffffffu, rs1, 2);
    const float inv0 = 1.f / rs0, inv1 = 1.f / rs1;
    float* sinv = (float*)sm;            // smem tiles no longer needed
    if ((lane & 3) == 0) {
        sinv[r0l] = inv0;
        sinv[r0l + 8] = inv1;
    }
    float* o0 = O + ((size_t)(b * S + q0 + r0l)) * D + colb;
    float* o1 = o0 + (size_t)8 * D;
#pragma unroll
    for (int j = 0; j < 16; j++) {
        *(float2*)(o0 + j * 8) = make_float2(oacc[j][0] * inv0, oacc[j][1] * inv0);
        *(float2*)(o1 + j * 8) = make_float2(oacc[j][2] * inv1, oacc[j][3] * inv1);
    }
    __syncthreads();

    // ---- tail: normalize this CTA's W strip in place ----
    // rows q0..q0+127; tiles 0..qt-1 are zero, tiles qt..15 scale by sinv[row].
    {
        float* wbase = W + ((size_t)(b * S + q0)) * S;
        const float4 z4 = make_float4(0.f, 0.f, 0.f, 0.f);
        for (int t = 0; t < qt; ++t) {
            float* wt = wbase + t * 128;
#pragma unroll 4
            for (int i = tid; i < 4096; i += 256) {
                const int row = i >> 5, c4 = (i & 31) * 4;
                __stcs((float4*)(wt + (size_t)row * S + c4), z4);
            }
        }
        for (int t = qt; t < 16; ++t) {
            float* wt = wbase + t * 128;
#pragma unroll 4
            for (int i = tid; i < 4096; i += 256) {
                const int row = i >> 5, c4 = (i & 31) * 4;
                const float inv = sinv[row];
                float4 v = *(float4*)(wt + (size_t)row * S + c4);
                v.x *= inv; v.y *= inv; v.z *= inv; v.w *= inv;
                __stcs((float4*)(wt + (size_t)row * S + c4), v);
            }
        }
    }
}

extern "C" void kernel_launch(void* const* d_in, const int* in_sizes, int n_in,
                              void* d_out, int out_size) {
    (void)in_sizes; (void)n_in; (void)out_size;
    const float* Q = (const float*)d_in[0];
    const float* K = (const float*)d_in[1];
    const float* V = (const float*)d_in[2];
    float* O = (float*)d_out;
    float* W = O + (size_t)Bn * S * D;

    cvt_k0<<<3 * 256, 256>>>(Q, K, V);
    cudaFuncSetAttribute(attn_k1, cudaFuncAttributeMaxDynamicSharedMemorySize, SMEM_SZ);
    attn_k1<<<256, 256, SMEM_SZ>>>(O, W);
}

// round 10
// speedup vs baseline: 1.3904x; 1.3904x over previous
#include <cuda_runtime.h>
#include <cuda_bf16.h>
#include <cstdint>

// B=16, S=2048, D=128 fp32.
// weights[b,q,k] = softmax_k over {k>=q} of <K[b,q,:],Q[b,k,:]>/sqrt(D); 0 elsewhere.
// outputs = weights @ V.   d_out = [outputs | weights].
//
// K0: split Q, K*scale, V into bf16 hi/lo 128x128 tiles (linear) in __device__ scratch.
// K1: per (q-tile 128, batch) CTA (LPT order). mma.sync bf16 3-split GEMMs, fully
//     unrolled. Epilogue FUSED into PV per k-tile: exp/mask/W-store/pack interleave
//     with PV MMAs (fills tensor-pipe gaps). cp.async double-buffered ingest.
// K2: normalize W rows (zeros below diagonal, scale above).

namespace {
constexpr int Bn = 16, S = 2048, D = 128;
constexpr int MT = 128;
constexpr float SCALE = 0.08838834764831845f;  // 1/sqrt(128)

constexpr int TILE_B = 65536;     // one tile pair: hi 32KB + lo 32KB
constexpr int SM_A  = 0;
constexpr int SM_Q  = 65536;
constexpr int SM_V  = 131072;
constexpr int SMEM_SZ = 196608;   // 192 KB
}

__device__ float g_inv[Bn * S];
__device__ __align__(16) uint8_t g_cvt[(size_t)3 * Bn * 16 * TILE_B];  // [tensor][b][tile]

// ---------------- helpers ----------------
__device__ __forceinline__ uint32_t smem_u32(const void* p) {
    uint32_t a;
    asm("{ .reg .u64 t; cvta.to.shared.u64 t, %1; cvt.u32.u64 %0, t; }" : "=r"(a) : "l"(p));
    return a;
}
__device__ __forceinline__ void ldsm4(uint32_t a, uint32_t& r0, uint32_t& r1,
                                      uint32_t& r2, uint32_t& r3) {
    asm volatile("ldmatrix.sync.aligned.m8n8.x4.shared.b16 {%0,%1,%2,%3}, [%4];"
                 : "=r"(r0), "=r"(r1), "=r"(r2), "=r"(r3) : "r"(a));
}
__device__ __forceinline__ void ldsm4t(uint32_t a, uint32_t& r0, uint32_t& r1,
                                       uint32_t& r2, uint32_t& r3) {
    asm volatile("ldmatrix.sync.aligned.m8n8.x4.trans.shared.b16 {%0,%1,%2,%3}, [%4];"
                 : "=r"(r0), "=r"(r1), "=r"(r2), "=r"(r3) : "r"(a));
}
__device__ __forceinline__ void mma16816(float* c, uint32_t a0, uint32_t a1, uint32_t a2,
                                         uint32_t a3, uint32_t b0, uint32_t b1) {
    asm volatile(
        "mma.sync.aligned.m16n8k16.row.col.f32.bf16.bf16.f32 "
        "{%0,%1,%2,%3}, {%4,%5,%6,%7}, {%8,%9}, {%0,%1,%2,%3};"
        : "+f"(c[0]), "+f"(c[1]), "+f"(c[2]), "+f"(c[3])
        : "r"(a0), "r"(a1), "r"(a2), "r"(a3), "r"(b0), "r"(b1));
}
__device__ __forceinline__ uint32_t pk_bf2(float x, float y) {
    __nv_bfloat162 t;
    t.x = __float2bfloat16(x);
    t.y = __float2bfloat16(y);
    return *(uint32_t*)&t;
}
__device__ __forceinline__ uint32_t pk_bf2_lo(float x, float y, uint32_t hi) {
    __nv_bfloat162 h = *(__nv_bfloat162*)&hi;
    __nv_bfloat162 t;
    t.x = __float2bfloat16(x - __bfloat162float(h.x));
    t.y = __float2bfloat16(y - __bfloat162float(h.y));
    return *(uint32_t*)&t;
}
// swizzled tile byte offset: [128 rows][256B], 16B chunk XOR (row&7)
__device__ __forceinline__ uint32_t sw_off(int row, int chunk) {
    return (uint32_t)(row * 256 + ((chunk ^ (row & 7)) << 4));
}
__device__ __forceinline__ void cpa16(uint32_t sdst, const void* gsrc) {
    asm volatile("cp.async.cg.shared.global [%0], [%1], 16;" :: "r"(sdst), "l"(gsrc));
}
#define CPA_COMMIT() asm volatile("cp.async.commit_group;" ::: "memory")
#define CPA_WAIT0()  asm volatile("cp.async.wait_group 0;" ::: "memory")

// global (linear pre-split tile) -> smem (swizzled), 64KB = hi+lo
__device__ __forceinline__ void tile_load(uint32_t sdst, const uint8_t* g, int tid) {
#pragma unroll
    for (int half = 0; half < 2; half++) {
#pragma unroll
        for (int j = 0; j < 8; j++) {
            int idx = j * 256 + tid;            // 0..2047
            int r = idx >> 4, cc = idx & 15;
            cpa16(sdst + half * 32768 + sw_off(r, cc), g + half * 32768 + (size_t)idx * 16);
        }
    }
}

// ------------------------------- K0: pre-split -------------------------------
__global__ __launch_bounds__(256)
void cvt_k0(const float* __restrict__ Q, const float* __restrict__ K,
            const float* __restrict__ V) {
    const int bx = blockIdx.x;                 // t*256 + b*16 + tile
    const int t = bx >> 8, rem = bx & 255;
    const int b = rem >> 4, tile = rem & 15;
    const float* src = (t == 0 ? Q : (t == 1 ? K : V)) + ((size_t)b * S + tile * 128) * D;
    const float mul = (t == 1) ? SCALE : 1.0f;
    uint8_t* dst = g_cvt + (size_t)bx * TILE_B;
    const int tid = threadIdx.x;
#pragma unroll
    for (int it = 0; it < 8; ++it) {
        int idx = it * 256 + tid;              // 0..2047 (16B chunk id)
        const float* gp = src + (size_t)idx * 8;
        float4 v0 = __ldcs((const float4*)gp);
        float4 v1 = __ldcs((const float4*)(gp + 4));
        v0.x *= mul; v0.y *= mul; v0.z *= mul; v0.w *= mul;
        v1.x *= mul; v1.y *= mul; v1.z *= mul; v1.w *= mul;
        uint32_t h0 = pk_bf2(v0.x, v0.y), h1 = pk_bf2(v0.z, v0.w);
        uint32_t h2 = pk_bf2(v1.x, v1.y), h3 = pk_bf2(v1.z, v1.w);
        uint32_t l0 = pk_bf2_lo(v0.x, v0.y, h0), l1 = pk_bf2_lo(v0.z, v0.w, h1);
        uint32_t l2 = pk_bf2_lo(v1.x, v1.y, h2), l3 = pk_bf2_lo(v1.z, v1.w, h3);
        *(uint4*)(dst + (size_t)idx * 16) = make_uint4(h0, h1, h2, h3);
        *(uint4*)(dst + 32768 + (size_t)idx * 16) = make_uint4(l0, l1, l2, l3);
    }
}

// ------------------------------- K1 -------------------------------
__global__ __launch_bounds__(256, 1)
void attn_k1(float* __restrict__ O, float* __restrict__ W) {
    extern __shared__ char sm[];
    const uint32_t sb = smem_u32(sm);
    const int tid = threadIdx.x, wid = tid >> 5, lane = tid & 31;
    // LPT order: big CTAs (qt=0, 16 chunks) first
    const int qt = blockIdx.x >> 4, b = blockIdx.x & 15;
    const int q0 = qt * MT;
    const int nc = 16 - qt;

    const uint8_t* scrQ = g_cvt + ((size_t)(0 * 256 + b * 16)) * TILE_B;
    const uint8_t* scrK = g_cvt + ((size_t)(1 * 256 + b * 16)) * TILE_B;
    const uint8_t* scrV = g_cvt + ((size_t)(2 * 256 + b * 16)) * TILE_B;

    // prologue: A (= K q-rows, pre-scaled) + Q(0)
    tile_load(sb + SM_A, scrK + (size_t)qt * TILE_B, tid);
    tile_load(sb + SM_Q, scrQ + (size_t)qt * TILE_B, tid);
    CPA_COMMIT();
    CPA_WAIT0();
    __syncthreads();

    float oacc[16][4];
#pragma unroll
    for (int j = 0; j < 16; j++)
#pragma unroll
        for (int e = 0; e < 4; e++) oacc[j][e] = 0.f;
    float rs0 = 0.f, rs1 = 0.f;

    const int lRow = lane & 15, lSel = lane >> 4;
    const int aRow = wid * 16 + lRow;
    const int r0l = wid * 16 + (lane >> 2);
    const int colb = 2 * (lane & 3);

    for (int c = 0; c < nc; ++c) {
        const int tileIdx = qt + c;
        // prefetch V(c) under scores
        tile_load(sb + SM_V, scrV + (size_t)tileIdx * TILE_B, tid);
        CPA_COMMIT();

        // ---- scores (3-split bf16), fully unrolled (static sacc indexing) ----
        float sacc[16][4];
#pragma unroll
        for (int j = 0; j < 16; j++)
#pragma unroll
            for (int e = 0; e < 4; e++) sacc[j][e] = 0.f;
        const bool diag = (c == 0);

#pragma unroll
        for (int ks = 0; ks < 8; ++ks) {
            uint32_t ah0, ah1, ah2, ah3, al0, al1, al2, al3;
            uint32_t aoff = sw_off(aRow, 2 * ks + lSel);
            ldsm4(sb + SM_A + aoff, ah0, ah1, ah2, ah3);
            ldsm4(sb + SM_A + 32768 + aoff, al0, al1, al2, al3);
#pragma unroll
            for (int jt = 0; jt < 8; ++jt) {
                // warp-uniform diagonal triangle skip; jt is compile-time constant
                if (!(diag && jt < wid)) {
                    uint32_t boff = sw_off(jt * 16 + lRow, 2 * ks + lSel);
                    uint32_t bh0, bh1, bh2, bh3, bl0, bl1, bl2, bl3;
                    ldsm4(sb + SM_Q + boff, bh0, bh1, bh2, bh3);
                    ldsm4(sb + SM_Q + 32768 + boff, bl0, bl1, bl2, bl3);
                    mma16816(sacc[2 * jt], ah0, ah1, ah2, ah3, bh0, bh2);
                    mma16816(sacc[2 * jt], al0, al1, al2, al3, bh0, bh2);
                    mma16816(sacc[2 * jt], ah0, ah1, ah2, ah3, bl0, bl2);
                    mma16816(sacc[2 * jt + 1], ah0, ah1, ah2, ah3, bh1, bh3);
                    mma16816(sacc[2 * jt + 1], al0, al1, al2, al3, bh1, bh3);
                    mma16816(sacc[2 * jt + 1], ah0, ah1, ah2, ah3, bl1, bl3);
                }
            }
        }

        CPA_WAIT0();        // V(c) resident
        __syncthreads();    // all warps done reading Q slot
        if (c + 1 < nc) {   // prefetch Q(c+1) under fused epilogue+PV
            tile_load(sb + SM_Q, scrQ + (size_t)(tileIdx + 1) * TILE_B, tid);
            CPA_COMMIT();
        }

        // ---- FUSED epilogue + PV per k-tile: exp/mask/W-store/pack interleaved
        //      with PV MMAs so MUFU/FMA/STG fill the tensor-pipe gaps ----
        float* w0 = W + ((size_t)(b * S + q0 + r0l)) * S + tileIdx * 128 + colb;
        float* w1 = w0 + (size_t)8 * S;
#pragma unroll
        for (int kt = 0; kt < 8; ++kt) {
            // epilogue for j = 2kt, 2kt+1 (cols kt*16 .. kt*16+15)
            const int j0 = 2 * kt, j1 = 2 * kt + 1;
            const int c0 = j0 * 8 + colb, c1 = j1 * 8 + colb;
            float e00 = (!diag || c0 >= r0l) ? __expf(sacc[j0][0]) : 0.f;
            float e01 = (!diag || c0 + 1 >= r0l) ? __expf(sacc[j0][1]) : 0.f;
            float f00 = (!diag || c0 >= r0l + 8) ? __expf(sacc[j0][2]) : 0.f;
            float f01 = (!diag || c0 + 1 >= r0l + 8) ? __expf(sacc[j0][3]) : 0.f;
            float e10 = (!diag || c1 >= r0l) ? __expf(sacc[j1][0]) : 0.f;
            float e11 = (!diag || c1 + 1 >= r0l) ? __expf(sacc[j1][1]) : 0.f;
            float f10 = (!diag || c1 >= r0l + 8) ? __expf(sacc[j1][2]) : 0.f;
            float f11 = (!diag || c1 + 1 >= r0l + 8) ? __expf(sacc[j1][3]) : 0.f;
            rs0 += e00 + e01 + e10 + e11;
            rs1 += f00 + f01 + f10 + f11;
            __stcs((float2*)(w0 + j0 * 8), make_float2(e00, e01));
            __stcs((float2*)(w1 + j0 * 8), make_float2(f00, f01));
            __stcs((float2*)(w0 + j1 * 8), make_float2(e10, e11));
            __stcs((float2*)(w1 + j1 * 8), make_float2(f10, f11));
            const uint32_t pa0 = pk_bf2(e00, e01);
            const uint32_t pa1 = pk_bf2(f00, f01);
            const uint32_t pa2 = pk_bf2(e10, e11);
            const uint32_t pa3 = pk_bf2(f10, f11);
            const uint32_t qa0 = pk_bf2_lo(e00, e01, pa0);
            const uint32_t qa1 = pk_bf2_lo(f00, f01, pa1);
            const uint32_t qa2 = pk_bf2_lo(e10, e11, pa2);
            const uint32_t qa3 = pk_bf2_lo(f10, f11, pa3);
            const int krow = kt * 16 + lRow;
#pragma unroll
            for (int dt = 0; dt < 8; ++dt) {
                uint32_t voff = sw_off(krow, 2 * dt + lSel);
                uint32_t vh0, vh1, vh2, vh3, vl0, vl1, vl2, vl3;
                ldsm4t(sb + SM_V + voff, vh0, vh1, vh2, vh3);
                ldsm4t(sb + SM_V + 32768 + voff, vl0, vl1, vl2, vl3);
                mma16816(oacc[2 * dt], pa0, pa1, pa2, pa3, vh0, vh1);
                mma16816(oacc[2 * dt], qa0, qa1, qa2, qa3, vh0, vh1);
                mma16816(oacc[2 * dt], pa0, pa1, pa2, pa3, vl0, vl1);
                mma16816(oacc[2 * dt + 1], pa0, pa1, pa2, pa3, vh2, vh3);
                mma16816(oacc[2 * dt + 1], qa0, qa1, qa2, qa3, vh2, vh3);
                mma16816(oacc[2 * dt + 1], pa0, pa1, pa2, pa3, vl2, vl3);
            }
        }
        CPA_WAIT0();        // Q(c+1) resident
        __syncthreads();    // all warps done reading V slot
    }

    // ---- rowsums -> inverses; scale O; write ----
    rs0 += __shfl_xor_sync(0xffffffffu, rs0, 1);
    rs0 += __shfl_xor_sync(0xffffffffu, rs0, 2);
    rs1 += __shfl_xor_sync(0xffffffffu, rs1, 1);
    rs1 += __shfl_xor_sync(0xffffffffu, rs1, 2);
    const float inv0 = 1.f / rs0, inv1 = 1.f / rs1;
    if ((lane & 3) == 0) {
        g_inv[b * S + q0 + r0l] = inv0;
        g_inv[b * S + q0 + r0l + 8] = inv1;
    }
    float* o0 = O + ((size_t)(b * S + q0 + r0l)) * D + colb;
    float* o1 = o0 + (size_t)8 * D;
#pragma unroll
    for (int j = 0; j < 16; j++) {
        *(float2*)(o0 + j * 8) = make_float2(oacc[j][0] * inv0, oacc[j][1] * inv0);
        *(float2*)(o1 + j * 8) = make_float2(oacc[j][2] * inv1, oacc[j][3] * inv1);
    }
}

// ------------------------------- K2: normalize W -------------------------------
__global__ __launch_bounds__(256)
void norm_w(float* __restrict__ W) {
    const int row = blockIdx.x;          // b*S + q
    const int q = row & (S - 1);
    const float inv = g_inv[row];
    float* wr = W + (size_t)row * S;
    const float4 z4 = make_float4(0.f, 0.f, 0.f, 0.f);
#pragma unroll 2
    for (int c = threadIdx.x * 4; c < S; c += 1024) {
        if (c + 4 <= q) {
            __stcs((float4*)(wr + c), z4);
        } else if (c >= q) {
            float4 v = __ldcs((const float4*)(wr + c));
            v.x *= inv; v.y *= inv; v.z *= inv; v.w *= inv;
            __stcs((float4*)(wr + c), v);
        } else {
            for (int j = 0; j < 4; j++) {
                int k = c + j;
                wr[k] = (k < q) ? 0.f : wr[k] * inv;
            }
        }
    }
}

extern "C" void kernel_launch(void* const* d_in, const int* in_sizes, int n_in,
                              void* d_out, int out_size) {
    (void)in_sizes; (void)n_in; (void)out_size;
    const float* Q = (const float*)d_in[0];
    const float* K = (const float*)d_in[1];
    const float* V = (const float*)d_in[2];
    float* O = (float*)d_out;
    float* W = O + (size_t)Bn * S * D;

    cvt_k0<<<3 * 256, 256>>>(Q, K, V);
    cudaFuncSetAttribute(attn_k1, cudaFuncAttributeMaxDynamicSharedMemorySize, SMEM_SZ);
    attn_k1<<<256, 256, SMEM_SZ>>>(O, W);
    norm_w<<<Bn * S, 256>>>(W);
}

// round 11
// speedup vs baseline: 1.4440x; 1.0386x over previous
#include <cuda_runtime.h>
#include <cuda_bf16.h>
#include <cuda_fp16.h>
#include <cstdint>

// B=16, S=2048, D=128 fp32.
// weights[b,q,k] = softmax_k over {k>=q} of <K[b,q,:],Q[b,k,:]>/sqrt(D); 0 elsewhere.
// outputs = weights @ V.   d_out = [outputs | weights].
//
// K0': split Q, K*scale, V into bf16 hi/lo tiles (scratch)  +  zero-fill W's
//      below-diagonal tiles (concurrent DRAM-bound CTAs in one launch).
// K1:  per (q-tile 128, batch) CTA (LPT). mma.sync bf16 3-split GEMMs, fused
//      exp/mask/pack/store epilogue inside PV. Unnormalized exp -> fp16 scratch.
// K2:  norm_w: scale-only — read fp16 scratch upper region, write normalized fp32 W.

namespace {
constexpr int Bn = 16, S = 2048, D = 128;
constexpr int MT = 128;
constexpr float SCALE = 0.08838834764831845f;  // 1/sqrt(128)

constexpr int TILE_B = 65536;     // one tile pair: hi 32KB + lo 32KB
constexpr int SM_A  = 0;
constexpr int SM_Q  = 65536;
constexpr int SM_V  = 131072;
constexpr int SMEM_SZ = 196608;   // 192 KB

constexpr int ZGRID = 16 * 120;   // below-diag zero tiles: per b, sum_{qt} qt = 120
}

__device__ float g_inv[Bn * S];
__device__ __align__(16) uint8_t g_cvt[(size_t)3 * Bn * 16 * TILE_B];  // [tensor][b][tile]
__device__ __align__(16) __half g_wt[(size_t)Bn * S * S];              // unnorm exp, fp16

// ---------------- helpers ----------------
__device__ __forceinline__ uint32_t smem_u32(const void* p) {
    uint32_t a;
    asm("{ .reg .u64 t; cvta.to.shared.u64 t, %1; cvt.u32.u64 %0, t; }" : "=r"(a) : "l"(p));
    return a;
}
__device__ __forceinline__ void ldsm4(uint32_t a, uint32_t& r0, uint32_t& r1,
                                      uint32_t& r2, uint32_t& r3) {
    asm volatile("ldmatrix.sync.aligned.m8n8.x4.shared.b16 {%0,%1,%2,%3}, [%4];"
                 : "=r"(r0), "=r"(r1), "=r"(r2), "=r"(r3) : "r"(a));
}
__device__ __forceinline__ void ldsm4t(uint32_t a, uint32_t& r0, uint32_t& r1,
                                       uint32_t& r2, uint32_t& r3) {
    asm volatile("ldmatrix.sync.aligned.m8n8.x4.trans.shared.b16 {%0,%1,%2,%3}, [%4];"
                 : "=r"(r0), "=r"(r1), "=r"(r2), "=r"(r3) : "r"(a));
}
__device__ __forceinline__ void mma16816(float* c, uint32_t a0, uint32_t a1, uint32_t a2,
                                         uint32_t a3, uint32_t b0, uint32_t b1) {
    asm volatile(
        "mma.sync.aligned.m16n8k16.row.col.f32.bf16.bf16.f32 "
        "{%0,%1,%2,%3}, {%4,%5,%6,%7}, {%8,%9}, {%0,%1,%2,%3};"
        : "+f"(c[0]), "+f"(c[1]), "+f"(c[2]), "+f"(c[3])
        : "r"(a0), "r"(a1), "r"(a2), "r"(a3), "r"(b0), "r"(b1));
}
__device__ __forceinline__ uint32_t pk_bf2(float x, float y) {
    __nv_bfloat162 t;
    t.x = __float2bfloat16(x);
    t.y = __float2bfloat16(y);
    return *(uint32_t*)&t;
}
__device__ __forceinline__ uint32_t pk_bf2_lo(float x, float y, uint32_t hi) {
    __nv_bfloat162 h = *(__nv_bfloat162*)&hi;
    __nv_bfloat162 t;
    t.x = __float2bfloat16(x - __bfloat162float(h.x));
    t.y = __float2bfloat16(y - __bfloat162float(h.y));
    return *(uint32_t*)&t;
}
__device__ __forceinline__ void stcs32(void* p, uint32_t v) {
    asm volatile("st.global.cs.b32 [%0], %1;" :: "l"(p), "r"(v) : "memory");
}
// swizzled tile byte offset: [128 rows][256B], 16B chunk XOR (row&7)
__device__ __forceinline__ uint32_t sw_off(int row, int chunk) {
    return (uint32_t)(row * 256 + ((chunk ^ (row & 7)) << 4));
}
__device__ __forceinline__ void cpa16(uint32_t sdst, const void* gsrc) {
    asm volatile("cp.async.cg.shared.global [%0], [%1], 16;" :: "r"(sdst), "l"(gsrc));
}
#define CPA_COMMIT() asm volatile("cp.async.commit_group;" ::: "memory")
#define CPA_WAIT0()  asm volatile("cp.async.wait_group 0;" ::: "memory")

// global (linear pre-split tile) -> smem (swizzled), 64KB = hi+lo
__device__ __forceinline__ void tile_load(uint32_t sdst, const uint8_t* g, int tid) {
#pragma unroll
    for (int half = 0; half < 2; half++) {
#pragma unroll
        for (int j = 0; j < 8; j++) {
            int idx = j * 256 + tid;            // 0..2047
            int r = idx >> 4, cc = idx & 15;
            cpa16(sdst + half * 32768 + sw_off(r, cc), g + half * 32768 + (size_t)idx * 16);
        }
    }
}

// ------------------- K0': pre-split + below-diagonal zero fill -------------------
__global__ __launch_bounds__(256)
void cvt_k0(const float* __restrict__ Q, const float* __restrict__ K,
            const float* __restrict__ V, float* __restrict__ W) {
    const int bx = blockIdx.x;
    const int tid = threadIdx.x;
    if (bx < 768) {                            // convert CTAs: t*256 + b*16 + tile
        const int t = bx >> 8, rem = bx & 255;
        const int b = rem >> 4, tile = rem & 15;
        const float* src = (t == 0 ? Q : (t == 1 ? K : V)) + ((size_t)b * S + tile * 128) * D;
        const float mul = (t == 1) ? SCALE : 1.0f;
        uint8_t* dst = g_cvt + (size_t)bx * TILE_B;
#pragma unroll
        for (int it = 0; it < 8; ++it) {
            int idx = it * 256 + tid;          // 16B chunk id
            const float* gp = src + (size_t)idx * 8;
            float4 v0 = __ldcs((const float4*)gp);
            float4 v1 = __ldcs((const float4*)(gp + 4));
            v0.x *= mul; v0.y *= mul; v0.z *= mul; v0.w *= mul;
            v1.x *= mul; v1.y *= mul; v1.z *= mul; v1.w *= mul;
            uint32_t h0 = pk_bf2(v0.x, v0.y), h1 = pk_bf2(v0.z, v0.w);
            uint32_t h2 = pk_bf2(v1.x, v1.y), h3 = pk_bf2(v1.z, v1.w);
            uint32_t l0 = pk_bf2_lo(v0.x, v0.y, h0), l1 = pk_bf2_lo(v0.z, v0.w, h1);
            uint32_t l2 = pk_bf2_lo(v1.x, v1.y, h2), l3 = pk_bf2_lo(v1.z, v1.w, h3);
            *(uint4*)(dst + (size_t)idx * 16) = make_uint4(h0, h1, h2, h3);
            *(uint4*)(dst + 32768 + (size_t)idx * 16) = make_uint4(l0, l1, l2, l3);
        }
    } else {                                   // zero CTAs: one 128x128 tile each
        int z = bx - 768;
        const int b = z / 120, p = z % 120;
        int qt = 1, cum = 0;
        while (p >= cum + qt + 1 && qt < 15) { cum += qt + 1; ++qt; }  // find qt: pairs (qt, t<=qt)... (see below)
        // simpler exact mapping: pairs ordered (qt=1..15, t=0..qt-1); cum before qt = qt*(qt-1)/2
        qt = 1;
        while (p >= (qt * (qt + 1)) / 2) ++qt;
        const int t = p - (qt * (qt - 1)) / 2;
        float* base = W + ((size_t)(b * S + qt * 128)) * S + t * 128;
        const float4 z4 = make_float4(0.f, 0.f, 0.f, 0.f);
#pragma unroll 4
        for (int i = tid; i < 4096; i += 256) {
            const int row = i >> 5, c4 = (i & 31) * 4;
            __stcs((float4*)(base + (size_t)row * S + c4), z4);
        }
    }
}

// ------------------------------- K1 -------------------------------
__global__ __launch_bounds__(256, 1)
void attn_k1(float* __restrict__ O) {
    extern __shared__ char sm[];
    const uint32_t sb = smem_u32(sm);
    const int tid = threadIdx.x, wid = tid >> 5, lane = tid & 31;
    // LPT order: big CTAs (qt=0, 16 chunks) first
    const int qt = blockIdx.x >> 4, b = blockIdx.x & 15;
    const int q0 = qt * MT;
    const int nc = 16 - qt;

    const uint8_t* scrQ = g_cvt + ((size_t)(0 * 256 + b * 16)) * TILE_B;
    const uint8_t* scrK = g_cvt + ((size_t)(1 * 256 + b * 16)) * TILE_B;
    const uint8_t* scrV = g_cvt + ((size_t)(2 * 256 + b * 16)) * TILE_B;

    tile_load(sb + SM_A, scrK + (size_t)qt * TILE_B, tid);
    tile_load(sb + SM_Q, scrQ + (size_t)qt * TILE_B, tid);
    CPA_COMMIT();
    CPA_WAIT0();
    __syncthreads();

    float oacc[16][4];
#pragma unroll
    for (int j = 0; j < 16; j++)
#pragma unroll
        for (int e = 0; e < 4; e++) oacc[j][e] = 0.f;
    float rs0 = 0.f, rs1 = 0.f;

    const int lRow = lane & 15, lSel = lane >> 4;
    const int aRow = wid * 16 + lRow;
    const int r0l = wid * 16 + (lane >> 2);
    const int colb = 2 * (lane & 3);

    for (int c = 0; c < nc; ++c) {
        const int tileIdx = qt + c;
        tile_load(sb + SM_V, scrV + (size_t)tileIdx * TILE_B, tid);
        CPA_COMMIT();

        // ---- scores (3-split bf16), fully unrolled ----
        float sacc[16][4];
#pragma unroll
        for (int j = 0; j < 16; j++)
#pragma unroll
            for (int e = 0; e < 4; e++) sacc[j][e] = 0.f;
        const bool diag = (c == 0);

#pragma unroll
        for (int ks = 0; ks < 8; ++ks) {
            uint32_t ah0, ah1, ah2, ah3, al0, al1, al2, al3;
            uint32_t aoff = sw_off(aRow, 2 * ks + lSel);
            ldsm4(sb + SM_A + aoff, ah0, ah1, ah2, ah3);
            ldsm4(sb + SM_A + 32768 + aoff, al0, al1, al2, al3);
#pragma unroll
            for (int jt = 0; jt < 8; ++jt) {
                if (!(diag && jt < wid)) {     // warp-uniform triangle skip
                    uint32_t boff = sw_off(jt * 16 + lRow, 2 * ks + lSel);
                    uint32_t bh0, bh1, bh2, bh3, bl0, bl1, bl2, bl3;
                    ldsm4(sb + SM_Q + boff, bh0, bh1, bh2, bh3);
                    ldsm4(sb + SM_Q + 32768 + boff, bl0, bl1, bl2, bl3);
                    mma16816(sacc[2 * jt], ah0, ah1, ah2, ah3, bh0, bh2);
                    mma16816(sacc[2 * jt], al0, al1, al2, al3, bh0, bh2);
                    mma16816(sacc[2 * jt], ah0, ah1, ah2, ah3, bl0, bl2);
                    mma16816(sacc[2 * jt + 1], ah0, ah1, ah2, ah3, bh1, bh3);
                    mma16816(sacc[2 * jt + 1], al0, al1, al2, al3, bh1, bh3);
                    mma16816(sacc[2 * jt + 1], ah0, ah1, ah2, ah3, bl1, bl3);
                }
            }
        }

        CPA_WAIT0();        // V(c) resident
        __syncthreads();    // all warps done reading Q slot
        if (c + 1 < nc) {
            tile_load(sb + SM_Q, scrQ + (size_t)(tileIdx + 1) * TILE_B, tid);
            CPA_COMMIT();
        }

        // ---- FUSED epilogue + PV per k-tile (exp/mask/fp16-store/pack in gaps) ----
        __half* w0 = g_wt + ((size_t)(b * S + q0 + r0l)) * S + tileIdx * 128 + colb;
        __half* w1 = w0 + (size_t)8 * S;
#pragma unroll
        for (int kt = 0; kt < 8; ++kt) {
            const int j0 = 2 * kt, j1 = 2 * kt + 1;
            const int c0 = j0 * 8 + colb, c1 = j1 * 8 + colb;
            float e00 = (!diag || c0 >= r0l) ? __expf(sacc[j0][0]) : 0.f;
            float e01 = (!diag || c0 + 1 >= r0l) ? __expf(sacc[j0][1]) : 0.f;
            float f00 = (!diag || c0 >= r0l + 8) ? __expf(sacc[j0][2]) : 0.f;
            float f01 = (!diag || c0 + 1 >= r0l + 8) ? __expf(sacc[j0][3]) : 0.f;
            float e10 = (!diag || c1 >= r0l) ? __expf(sacc[j1][0]) : 0.f;
            float e11 = (!diag || c1 + 1 >= r0l) ? __expf(sacc[j1][1]) : 0.f;
            float f10 = (!diag || c1 >= r0l + 8) ? __expf(sacc[j1][2]) : 0.f;
            float f11 = (!diag || c1 + 1 >= r0l + 8) ? __expf(sacc[j1][3]) : 0.f;
            rs0 += e00 + e01 + e10 + e11;
            rs1 += f00 + f01 + f10 + f11;
            {   // fp16 unnormalized-weight stores (4B per thread, streaming)
                __half2 a = __floats2half2_rn(e00, e01), bq = __floats2half2_rn(f00, f01);
                __half2 cc = __floats2half2_rn(e10, e11), d = __floats2half2_rn(f10, f11);
                stcs32(w0 + j0 * 8, *(uint32_t*)&a);
                stcs32(w1 + j0 * 8, *(uint32_t*)&bq);
                stcs32(w0 + j1 * 8, *(uint32_t*)&cc);
                stcs32(w1 + j1 * 8, *(uint32_t*)&d);
            }
            const uint32_t pa0 = pk_bf2(e00, e01);
            const uint32_t pa1 = pk_bf2(f00, f01);
            const uint32_t pa2 = pk_bf2(e10, e11);
            const uint32_t pa3 = pk_bf2(f10, f11);
            const uint32_t qa0 = pk_bf2_lo(e00, e01, pa0);
            const uint32_t qa1 = pk_bf2_lo(f00, f01, pa1);
            const uint32_t qa2 = pk_bf2_lo(e10, e11, pa2);
            const uint32_t qa3 = pk_bf2_lo(f10, f11, pa3);
            const int krow = kt * 16 + lRow;
#pragma unroll
            for (int dt = 0; dt < 8; ++dt) {
                uint32_t voff = sw_off(krow, 2 * dt + lSel);
                uint32_t vh0, vh1, vh2, vh3, vl0, vl1, vl2, vl3;
                ldsm4t(sb + SM_V + voff, vh0, vh1, vh2, vh3);
                ldsm4t(sb + SM_V + 32768 + voff, vl0, vl1, vl2, vl3);
                mma16816(oacc[2 * dt], pa0, pa1, pa2, pa3, vh0, vh1);
                mma16816(oacc[2 * dt], qa0, qa1, qa2, qa3, vh0, vh1);
                mma16816(oacc[2 * dt], pa0, pa1, pa2, pa3, vl0, vl1);
                mma16816(oacc[2 * dt + 1], pa0, pa1, pa2, pa3, vh2, vh3);
                mma16816(oacc[2 * dt + 1], qa0, qa1, qa2, qa3, vh2, vh3);
                mma16816(oacc[2 * dt + 1], pa0, pa1, pa2, pa3, vl2, vl3);
            }
        }
        CPA_WAIT0();        // Q(c+1) resident
        __syncthreads();    // all warps done reading V slot
    }

    // ---- rowsums -> inverses; scale O; write ----
    rs0 += __shfl_xor_sync(0xffffffffu, rs0, 1);
    rs0 += __shfl_xor_sync(0xffffffffu, rs0, 2);
    rs1 += __shfl_xor_sync(0xffffffffu, rs1, 1);
    rs1 += __shfl_xor_sync(0xffffffffu, rs1, 2);
    const float inv0 = 1.f / rs0, inv1 = 1.f / rs1;
    if ((lane & 3) == 0) {
        g_inv[b * S + q0 + r0l] = inv0;
        g_inv[b * S + q0 + r0l + 8] = inv1;
    }
    float* o0 = O + ((size_t)(b * S + q0 + r0l)) * D + colb;
    float* o1 = o0 + (size_t)8 * D;
#pragma unroll
    for (int j = 0; j < 16; j++) {
        *(float2*)(o0 + j * 8) = make_float2(oacc[j][0] * inv0, oacc[j][1] * inv0);
        *(float2*)(o1 + j * 8) = make_float2(oacc[j][2] * inv1, oacc[j][3] * inv1);
    }
}

// --------------- K2: scale-only normalize (upper region) ---------------
__global__ __launch_bounds__(256)
void norm_w(float* __restrict__ W) {
    const int row = blockIdx.x;          // b*S + q
    const int q = row & (S - 1);
    const float inv = g_inv[row];
    const int cstart = (q >> 7) << 7;    // first tile column K1 wrote
    const __half* src = g_wt + (size_t)row * S;
    float* dst = W + (size_t)row * S;
    // each thread: 8 halves (16B read) -> 8 floats (32B write)
    const int c = cstart + threadIdx.x * 8;
    if (c < S) {
        uint4 u = __ldcs((const uint4*)(src + c));
        const __half2* hp = (const __half2*)&u;
        float2 f0 = __half22float2(hp[0]), f1 = __half22float2(hp[1]);
        float2 f2 = __half22float2(hp[2]), f3 = __half22float2(hp[3]);
        float4 o0 = make_float4(f0.x * inv, f0.y * inv, f1.x * inv, f1.y * inv);
        float4 o1 = make_float4(f2.x * inv, f2.y * inv, f3.x * inv, f3.y * inv);
        __stcs((float4*)(dst + c), o0);
        __stcs((float4*)(dst + c + 4), o1);
    }
}

extern "C" void kernel_launch(void* const* d_in, const int* in_sizes, int n_in,
                              void* d_out, int out_size) {
    (void)in_sizes; (void)n_in; (void)out_size;
    const float* Q = (const float*)d_in[0];
    const float* K = (const float*)d_in[1];
    const float* V = (const float*)d_in[2];
    float* O = (float*)d_out;
    float* W = O + (size_t)Bn * S * D;

    cvt_k0<<<768 + ZGRID, 256>>>(Q, K, V, W);
    cudaFuncSetAttribute(attn_k1, cudaFuncAttributeMaxDynamicSharedMemorySize, SMEM_SZ);
    attn_k1<<<256, 256, SMEM_SZ>>>(O);
    norm_w<<<Bn * S, 256>>>(W);
}

// round 12
// speedup vs baseline: 1.5002x; 1.0389x over previous
#include <cuda_runtime.h>
#include <cuda_bf16.h>
#include <cuda_fp16.h>
#include <cstdint>

// B=16, S=2048, D=128 fp32.
// weights[b,q,k] = softmax_k over {k>=q} of <K[b,q,:],Q[b,k,:]>/sqrt(D); 0 elsewhere.
// outputs = weights @ V.   d_out = [outputs | weights].
//
// K0': split Q, K*scale, V into bf16 hi/lo 64-row tiles (scratch) + zero-fill W's
//      below-diagonal 128x128 tiles.
// K1:  MT=64/NT=64, 128 threads, 96KB smem -> 2 CTAs/SM (independent sync domains).
//      mma.sync bf16 3-split GEMMs, fused exp/mask/pack/fp16-store epilogue in PV.
// K2:  norm_w: zero the 64-col odd-strip, scale the rest from fp16 scratch.

namespace {
constexpr int Bn = 16, S = 2048, D = 128;
constexpr float SCALE = 0.08838834764831845f;  // 1/sqrt(128)

constexpr int TQ = 32768;         // one 64-row tile pair: hi 16KB + lo 16KB
constexpr int SM_A = 0;
constexpr int SM_Q = 32768;
constexpr int SM_V = 65536;
constexpr int SMEM_SZ = 98304;    // 96 KB -> 2 CTAs/SM

constexpr int ZGRID = 16 * 120;   // below-diag zero tiles (128x128 granularity)
}

__device__ float g_inv[Bn * S];
__device__ __align__(16) uint8_t g_cvt[(size_t)3 * Bn * 32 * TQ];   // [tensor][b][t64]
__device__ __align__(16) __half g_wt[(size_t)Bn * S * S];           // unnorm exp, fp16

// ---------------- helpers ----------------
__device__ __forceinline__ uint32_t smem_u32(const void* p) {
    uint32_t a;
    asm("{ .reg .u64 t; cvta.to.shared.u64 t, %1; cvt.u32.u64 %0, t; }" : "=r"(a) : "l"(p));
    return a;
}
__device__ __forceinline__ void ldsm4(uint32_t a, uint32_t& r0, uint32_t& r1,
                                      uint32_t& r2, uint32_t& r3) {
    asm volatile("ldmatrix.sync.aligned.m8n8.x4.shared.b16 {%0,%1,%2,%3}, [%4];"
                 : "=r"(r0), "=r"(r1), "=r"(r2), "=r"(r3) : "r"(a));
}
__device__ __forceinline__ void ldsm4t(uint32_t a, uint32_t& r0, uint32_t& r1,
                                       uint32_t& r2, uint32_t& r3) {
    asm volatile("ldmatrix.sync.aligned.m8n8.x4.trans.shared.b16 {%0,%1,%2,%3}, [%4];"
                 : "=r"(r0), "=r"(r1), "=r"(r2), "=r"(r3) : "r"(a));
}
__device__ __forceinline__ void mma16816(float* c, uint32_t a0, uint32_t a1, uint32_t a2,
                                         uint32_t a3, uint32_t b0, uint32_t b1) {
    asm volatile(
        "mma.sync.aligned.m16n8k16.row.col.f32.bf16.bf16.f32 "
        "{%0,%1,%2,%3}, {%4,%5,%6,%7}, {%8,%9}, {%0,%1,%2,%3};"
        : "+f"(c[0]), "+f"(c[1]), "+f"(c[2]), "+f"(c[3])
        : "r"(a0), "r"(a1), "r"(a2), "r"(a3), "r"(b0), "r"(b1));
}
__device__ __forceinline__ uint32_t pk_bf2(float x, float y) {
    __nv_bfloat162 t;
    t.x = __float2bfloat16(x);
    t.y = __float2bfloat16(y);
    return *(uint32_t*)&t;
}
__device__ __forceinline__ uint32_t pk_bf2_lo(float x, float y, uint32_t hi) {
    __nv_bfloat162 h = *(__nv_bfloat162*)&hi;
    __nv_bfloat162 t;
    t.x = __float2bfloat16(x - __bfloat162float(h.x));
    t.y = __float2bfloat16(y - __bfloat162float(h.y));
    return *(uint32_t*)&t;
}
__device__ __forceinline__ void stcs32(void* p, uint32_t v) {
    asm volatile("st.global.cs.b32 [%0], %1;" :: "l"(p), "r"(v) : "memory");
}
// swizzled tile byte offset within a 64-row half-tile: row*256B, 16B chunk XOR (row&7)
__device__ __forceinline__ uint32_t sw_off(int row, int chunk) {
    return (uint32_t)(row * 256 + ((chunk ^ (row & 7)) << 4));
}
__device__ __forceinline__ void cpa16(uint32_t sdst, const void* gsrc) {
    asm volatile("cp.async.cg.shared.global [%0], [%1], 16;" :: "r"(sdst), "l"(gsrc));
}
#define CPA_COMMIT() asm volatile("cp.async.commit_group;" ::: "memory")
#define CPA_WAIT0()  asm volatile("cp.async.wait_group 0;" ::: "memory")

// global (linear 64-row tile pair) -> smem (swizzled), 32KB, 128 threads
__device__ __forceinline__ void tile_load(uint32_t sdst, const uint8_t* g, int tid) {
#pragma unroll
    for (int half = 0; half < 2; half++) {
#pragma unroll
        for (int j = 0; j < 8; j++) {
            int idx = j * 128 + tid;            // 0..1023
            int r = idx >> 4, cc = idx & 15;
            cpa16(sdst + half * 16384 + sw_off(r, cc), g + half * 16384 + (size_t)idx * 16);
        }
    }
}

// ------------------- K0': pre-split (64-row tiles) + zero fill -------------------
__global__ __launch_bounds__(256)
void cvt_k0(const float* __restrict__ Q, const float* __restrict__ K,
            const float* __restrict__ V, float* __restrict__ W) {
    const int bx = blockIdx.x;
    const int tid = threadIdx.x;
    if (bx < 768) {                            // convert CTAs: t*256 + b*16 + tile128
        const int t = bx >> 8, rem = bx & 255;
        const int b = rem >> 4, tile = rem & 15;
        const float* src = (t == 0 ? Q : (t == 1 ? K : V)) + ((size_t)b * S + tile * 128) * D;
        const float mul = (t == 1) ? SCALE : 1.0f;
        uint8_t* dst = g_cvt + ((size_t)((t * 16 + b) * 32 + tile * 2)) * TQ;
#pragma unroll
        for (int it = 0; it < 8; ++it) {
            int idx = it * 256 + tid;          // 16B chunk id, row = idx>>4 (0..127)
            const int row = idx >> 4, cc = idx & 15;
            const int t64 = row >> 6, r63 = row & 63;
            const size_t lin = (size_t)(r63 * 16 + cc) * 16;
            uint8_t* tp = dst + (size_t)t64 * TQ;
            const float* gp = src + (size_t)idx * 8;
            float4 v0 = __ldcs((const float4*)gp);
            float4 v1 = __ldcs((const float4*)(gp + 4));
            v0.x *= mul; v0.y *= mul; v0.z *= mul; v0.w *= mul;
            v1.x *= mul; v1.y *= mul; v1.z *= mul; v1.w *= mul;
            uint32_t h0 = pk_bf2(v0.x, v0.y), h1 = pk_bf2(v0.z, v0.w);
            uint32_t h2 = pk_bf2(v1.x, v1.y), h3 = pk_bf2(v1.z, v1.w);
            uint32_t l0 = pk_bf2_lo(v0.x, v0.y, h0), l1 = pk_bf2_lo(v0.z, v0.w, h1);
            uint32_t l2 = pk_bf2_lo(v1.x, v1.y, h2), l3 = pk_bf2_lo(v1.z, v1.w, h3);
            *(uint4*)(tp + lin) = make_uint4(h0, h1, h2, h3);
            *(uint4*)(tp + 16384 + lin) = make_uint4(l0, l1, l2, l3);
        }
    } else {                                   // zero CTAs: one 128x128 tile each
        int z = bx - 768;
        const int b = z / 120, p = z % 120;
        int qt = 1;
        while (p >= (qt * (qt + 1)) / 2) ++qt;
        const int t = p - (qt * (qt - 1)) / 2;
        float* base = W + ((size_t)(b * S + qt * 128)) * S + t * 128;
        const float4 z4 = make_float4(0.f, 0.f, 0.f, 0.f);
#pragma unroll 4
        for (int i = tid; i < 4096; i += 256) {
            const int row = i >> 5, c4 = (i & 31) * 4;
            __stcs((float4*)(base + (size_t)row * S + c4), z4);
        }
    }
}

// ------------------------------- K1 -------------------------------
__global__ __launch_bounds__(128, 2)
void attn_k1(float* __restrict__ O) {
    extern __shared__ char sm[];
    const uint32_t sb = smem_u32(sm);
    const int tid = threadIdx.x, wid = tid >> 5, lane = tid & 31;
    // LPT order: big CTAs (qt=0, 32 chunks) first
    const int qt = blockIdx.x >> 4, b = blockIdx.x & 15;   // qt 0..31
    const int q0 = qt * 64;
    const int nc = 32 - qt;

    const uint8_t* scrQ = g_cvt + ((size_t)((0 * 16 + b) * 32)) * TQ;
    const uint8_t* scrK = g_cvt + ((size_t)((1 * 16 + b) * 32)) * TQ;
    const uint8_t* scrV = g_cvt + ((size_t)((2 * 16 + b) * 32)) * TQ;

    tile_load(sb + SM_A, scrK + (size_t)qt * TQ, tid);
    tile_load(sb + SM_Q, scrQ + (size_t)qt * TQ, tid);
    CPA_COMMIT();
    CPA_WAIT0();
    __syncthreads();

    float oacc[16][4];
#pragma unroll
    for (int j = 0; j < 16; j++)
#pragma unroll
        for (int e = 0; e < 4; e++) oacc[j][e] = 0.f;
    float rs0 = 0.f, rs1 = 0.f;

    const int lRow = lane & 15, lSel = lane >> 4;
    const int aRow = wid * 16 + lRow;          // 0..63
    const int r0l = wid * 16 + (lane >> 2);    // 0..63
    const int colb = 2 * (lane & 3);

    for (int c = 0; c < nc; ++c) {
        const int tileIdx = qt + c;
        tile_load(sb + SM_V, scrV + (size_t)tileIdx * TQ, tid);
        CPA_COMMIT();

        // ---- scores (3-split bf16), fully unrolled ----
        float sacc[8][4];
#pragma unroll
        for (int j = 0; j < 8; j++)
#pragma unroll
            for (int e = 0; e < 4; e++) sacc[j][e] = 0.f;
        const bool diag = (c == 0);

#pragma unroll
        for (int ks = 0; ks < 8; ++ks) {
            uint32_t ah0, ah1, ah2, ah3, al0, al1, al2, al3;
            uint32_t aoff = sw_off(aRow, 2 * ks + lSel);
            ldsm4(sb + SM_A + aoff, ah0, ah1, ah2, ah3);
            ldsm4(sb + SM_A + 16384 + aoff, al0, al1, al2, al3);
#pragma unroll
            for (int jt = 0; jt < 4; ++jt) {
                if (!(diag && jt < wid)) {     // warp-uniform triangle skip
                    uint32_t boff = sw_off(jt * 16 + lRow, 2 * ks + lSel);
                    uint32_t bh0, bh1, bh2, bh3, bl0, bl1, bl2, bl3;
                    ldsm4(sb + SM_Q + boff, bh0, bh1, bh2, bh3);
                    ldsm4(sb + SM_Q + 16384 + boff, bl0, bl1, bl2, bl3);
                    mma16816(sacc[2 * jt], ah0, ah1, ah2, ah3, bh0, bh2);
                    mma16816(sacc[2 * jt], al0, al1, al2, al3, bh0, bh2);
                    mma16816(sacc[2 * jt], ah0, ah1, ah2, ah3, bl0, bl2);
                    mma16816(sacc[2 * jt + 1], ah0, ah1, ah2, ah3, bh1, bh3);
                    mma16816(sacc[2 * jt + 1], al0, al1, al2, al3, bh1, bh3);
                    mma16816(sacc[2 * jt + 1], ah0, ah1, ah2, ah3, bl1, bl3);
                }
            }
        }

        CPA_WAIT0();        // V(c) resident
        __syncthreads();    // all warps done reading Q slot
        if (c + 1 < nc) {
            tile_load(sb + SM_Q, scrQ + (size_t)(tileIdx + 1) * TQ, tid);
            CPA_COMMIT();
        }

        // ---- FUSED epilogue + PV per k-tile ----
        __half* w0 = g_wt + ((size_t)(b * S + q0 + r0l)) * S + tileIdx * 64 + colb;
        __half* w1 = w0 + (size_t)8 * S;
#pragma unroll
        for (int kt = 0; kt < 4; ++kt) {
            const int j0 = 2 * kt, j1 = 2 * kt + 1;
            const int c0 = j0 * 8 + colb, c1 = j1 * 8 + colb;
            float e00 = (!diag || c0 >= r0l) ? __expf(sacc[j0][0]) : 0.f;
            float e01 = (!diag || c0 + 1 >= r0l) ? __expf(sacc[j0][1]) : 0.f;
            float f00 = (!diag || c0 >= r0l + 8) ? __expf(sacc[j0][2]) : 0.f;
            float f01 = (!diag || c0 + 1 >= r0l + 8) ? __expf(sacc[j0][3]) : 0.f;
            float e10 = (!diag || c1 >= r0l) ? __expf(sacc[j1][0]) : 0.f;
            float e11 = (!diag || c1 + 1 >= r0l) ? __expf(sacc[j1][1]) : 0.f;
            float f10 = (!diag || c1 >= r0l + 8) ? __expf(sacc[j1][2]) : 0.f;
            float f11 = (!diag || c1 + 1 >= r0l + 8) ? __expf(sacc[j1][3]) : 0.f;
            rs0 += e00 + e01 + e10 + e11;
            rs1 += f00 + f01 + f10 + f11;
            {
                __half2 a = __floats2half2_rn(e00, e01), bq = __floats2half2_rn(f00, f01);
                __half2 cc = __floats2half2_rn(e10, e11), d = __floats2half2_rn(f10, f11);
                stcs32(w0 + j0 * 8, *(uint32_t*)&a);
                stcs32(w1 + j0 * 8, *(uint32_t*)&bq);
                stcs32(w0 + j1 * 8, *(uint32_t*)&cc);
                stcs32(w1 + j1 * 8, *(uint32_t*)&d);
            }
            const uint32_t pa0 = pk_bf2(e00, e01);
            const uint32_t pa1 = pk_bf2(f00, f01);
            const uint32_t pa2 = pk_bf2(e10, e11);
            const uint32_t pa3 = pk_bf2(f10, f11);
            const uint32_t qa0 = pk_bf2_lo(e00, e01, pa0);
            const uint32_t qa1 = pk_bf2_lo(f00, f01, pa1);
            const uint32_t qa2 = pk_bf2_lo(e10, e11, pa2);
            const uint32_t qa3 = pk_bf2_lo(f10, f11, pa3);
            const int krow = kt * 16 + lRow;
#pragma unroll
            for (int dt = 0; dt < 8; ++dt) {
                uint32_t voff = sw_off(krow, 2 * dt + lSel);
                uint32_t vh0, vh1, vh2, vh3, vl0, vl1, vl2, vl3;
                ldsm4t(sb + SM_V + voff, vh0, vh1, vh2, vh3);
                ldsm4t(sb + SM_V + 16384 + voff, vl0, vl1, vl2, vl3);
                mma16816(oacc[2 * dt], pa0, pa1, pa2, pa3, vh0, vh1);
                mma16816(oacc[2 * dt], qa0, qa1, qa2, qa3, vh0, vh1);
                mma16816(oacc[2 * dt], pa0, pa1, pa2, pa3, vl0, vl1);
                mma16816(oacc[2 * dt + 1], pa0, pa1, pa2, pa3, vh2, vh3);
                mma16816(oacc[2 * dt + 1], qa0, qa1, qa2, qa3, vh2, vh3);
                mma16816(oacc[2 * dt + 1], pa0, pa1, pa2, pa3, vl2, vl3);
            }
        }
        CPA_WAIT0();        // Q(c+1) resident
        __syncthreads();    // all warps done reading V slot
    }

    // ---- rowsums -> inverses; scale O; write ----
    rs0 += __shfl_xor_sync(0xffffffffu, rs0, 1);
    rs0 += __shfl_xor_sync(0xffffffffu, rs0, 2);
    rs1 += __shfl_xor_sync(0xffffffffu, rs1, 1);
    rs1 += __shfl_xor_sync(0xffffffffu, rs1, 2);
    const float inv0 = 1.f / rs0, inv1 = 1.f / rs1;
    if ((lane & 3) == 0) {
        g_inv[b * S + q0 + r0l] = inv0;
        g_inv[b * S + q0 + r0l + 8] = inv1;
    }
    float* o0 = O + ((size_t)(b * S + q0 + r0l)) * D + colb;
    float* o1 = o0 + (size_t)8 * D;
#pragma unroll
    for (int j = 0; j < 16; j++) {
        *(float2*)(o0 + j * 8) = make_float2(oacc[j][0] * inv0, oacc[j][1] * inv0);
        *(float2*)(o1 + j * 8) = make_float2(oacc[j][2] * inv1, oacc[j][3] * inv1);
    }
}

// --------------- K2: zero odd-strip + scale-normalize (upper region) ---------------
__global__ __launch_bounds__(256)
void norm_w(float* __restrict__ W) {
    const int row = blockIdx.x;          // b*S + q
    const int q = row & (S - 1);
    const float inv = g_inv[row];
    const int base128 = (q >> 7) << 7;   // zero kernel handled cols < base128
    const int cstart = (q >> 6) << 6;    // K1 wrote from here
    const __half* src = g_wt + (size_t)row * S;
    float* dst = W + (size_t)row * S;
    const int c = base128 + threadIdx.x * 8;
    if (c < S) {
        if (c < cstart) {                // 64-col strip (odd 64-tiles): pure zeros
            const float4 z4 = make_float4(0.f, 0.f, 0.f, 0.f);
            __stcs((float4*)(dst + c), z4);
            __stcs((float4*)(dst + c + 4), z4);
        } else {
            uint4 u = __ldcs((const uint4*)(src + c));
            const __half2* hp = (const __half2*)&u;
            float2 f0 = __half22float2(hp[0]), f1 = __half22float2(hp[1]);
            float2 f2 = __half22float2(hp[2]), f3 = __half22float2(hp[3]);
            float4 o0 = make_float4(f0.x * inv, f0.y * inv, f1.x * inv, f1.y * inv);
            float4 o1 = make_float4(f2.x * inv, f2.y * inv, f3.x * inv, f3.y * inv);
            __stcs((float4*)(dst + c), o0);
            __stcs((float4*)(dst + c + 4), o1);
        }
    }
}

extern "C" void kernel_launch(void* const* d_in, const int* in_sizes, int n_in,
                              void* d_out, int out_size) {
    (void)in_sizes; (void)n_in; (void)out_size;
    const float* Q = (const float*)d_in[0];
    const float* K = (const float*)d_in[1];
    const float* V = (const float*)d_in[2];
    float* O = (float*)d_out;
    float* W = O + (size_t)Bn * S * D;

    cvt_k0<<<768 + ZGRID, 256>>>(Q, K, V, W);
    cudaFuncSetAttribute(attn_k1, cudaFuncAttributeMaxDynamicSharedMemorySize, SMEM_SZ);
    attn_k1<<<512, 128, SMEM_SZ>>>(O);
    norm_w<<<Bn * S, 256>>>(W);
}